// round 7
// baseline (speedup 1.0000x reference)
#include <cuda_runtime.h>
#include <cuda_bf16.h>
#include <stdint.h>

// PointPillars BEV scatter as a full-output gather, channel-quad version,
// with a SELF-VALIDATING pillar map (no init/clear kernel needed).
//
//   out(B, C, H, W): out[b,c,y,x] = feat[m, c] where map[b,y,x] == m+1 and
//   coords[m] maps back to (b,y,x); otherwise 0.
//
// Map entries are never cleared: 0 (static zero-init) means empty; any
// nonzero entry is validated against coords, so stale/garbage content can
// never produce wrong output. Output depends only on current inputs.

#define BEV_H 496
#define BEV_W 432
#define C_CH  64
#define HW    (BEV_H * BEV_W)     // 214,272
#define HW4   (HW / 4)            // 53,568
#define MAXB  8

__device__ int g_pillar_map[MAXB * HW];   // zero-initialized at module load

// ---------------------------------------------------------------------------
// Kernel 1: scatter pillar indices (+1) into the map.
// coords layout: (M, 3) int32 rows [b, y, x]; collision-free by construction.
// ---------------------------------------------------------------------------
__global__ void scatter_map_kernel(const int* __restrict__ coords, int M) {
    int m = blockIdx.x * blockDim.x + threadIdx.x;
    if (m < M) {
        int b = coords[3 * m + 0];
        int y = coords[3 * m + 1];
        int x = coords[3 * m + 2];
        g_pillar_map[b * HW + y * BEV_W + x] = m + 1;
    }
}

// ---------------------------------------------------------------------------
// Kernel 2: gather. Thread i -> (b, c4, r):
//   b = batch, c4 = channel quad (0..15), r = cell quad within plane.
// One int4 map read, <=4 validated LDG.128 feature reads, 4 coalesced
// STG.128 streaming stores into 4 consecutive channel planes.
// ---------------------------------------------------------------------------
__global__ void __launch_bounds__(256) gather_out_kernel(
    const int*   __restrict__ coords, // (M, 3)
    const float* __restrict__ feat,   // (M, 64)
    float* __restrict__ out,          // (B, 64, H, W)
    int M,
    int n16)                          // out_size / 16
{
    int i = blockIdx.x * blockDim.x + threadIdx.x;
    if (i >= n16) return;

    int r  = i % HW4;                 // cell-quad index within plane
    int t  = i / HW4;                 // b*16 + c4
    int c4 = t & 15;
    int b  = t >> 4;

    int cell0 = b * HW + 4 * r;       // flat (b,y,x) of first cell in quad

    // Coalesced 16B map read.
    int4 m4 = *reinterpret_cast<const int4*>(&g_pillar_map[cell0]);

    int cbase = c4 * 4;
    const float4 z4 = make_float4(0.f, 0.f, 0.f, 0.f);

    // Validate a map entry v for flat cell 'cell': nonzero, in-range, and
    // coords[v-1] maps back to exactly this cell. Any stale/garbage entry
    // fails -> zero. Occupied-cell coords rows are read by all 16 channel-
    // quad threads of that cell -> L1/L2 broadcast hits.
    #define FETCH(v, cellofs, dst)                                           \
    {                                                                        \
        float4 fv = z4;                                                      \
        int vm = (v) - 1;                                                    \
        if ((unsigned)vm < (unsigned)M) {                                    \
            int cb = __ldg(&coords[3 * vm + 0]);                             \
            int cy = __ldg(&coords[3 * vm + 1]);                             \
            int cx = __ldg(&coords[3 * vm + 2]);                             \
            if (cb * HW + cy * BEV_W + cx == cell0 + (cellofs))              \
                fv = __ldg(reinterpret_cast<const float4*>(                  \
                         &feat[vm * C_CH + cbase]));                         \
        }                                                                    \
        dst = fv;                                                            \
    }

    float4 f0, f1, f2, f3;
    FETCH(m4.x, 0, f0);
    FETCH(m4.y, 1, f1);
    FETCH(m4.z, 2, f2);
    FETCH(m4.w, 3, f3);
    #undef FETCH

    // f0 = channels cbase..cbase+3 of cell0, etc. Transpose 4x4 in registers
    // to get per-channel vectors over the 4 cells.
    float4 o0 = make_float4(f0.x, f1.x, f2.x, f3.x);
    float4 o1 = make_float4(f0.y, f1.y, f2.y, f3.y);
    float4 o2 = make_float4(f0.z, f1.z, f2.z, f3.z);
    float4 o3 = make_float4(f0.w, f1.w, f2.w, f3.w);

    // Coalesced streaming stores into 4 channel planes.
    long base = (long)(b * C_CH + cbase) * HW + 4 * r;
    __stcs(reinterpret_cast<float4*>(&out[base + 0L * HW]), o0);
    __stcs(reinterpret_cast<float4*>(&out[base + 1L * HW]), o1);
    __stcs(reinterpret_cast<float4*>(&out[base + 2L * HW]), o2);
    __stcs(reinterpret_cast<float4*>(&out[base + 3L * HW]), o3);
}

// ---------------------------------------------------------------------------
// Launch
// Inputs: [0] voxel_coords (M,3) int32, [1] voxel_features (M,64) f32,
//         [2] batch_size scalar (B derived from out_size instead).
// Output: (B, 64, 496, 432) float32
// ---------------------------------------------------------------------------
extern "C" void kernel_launch(void* const* d_in, const int* in_sizes, int n_in,
                              void* d_out, int out_size) {
    const int*   coords = (const int*)d_in[0];
    const float* feat   = (const float*)d_in[1];
    float*       out    = (float*)d_out;

    int M = in_sizes[0] / 3;
    int B = out_size / (C_CH * HW);
    if (B < 1) B = 1;
    if (B > MAXB) B = MAXB;

    scatter_map_kernel<<<(M + 255) / 256, 256>>>(coords, M);

    int n16 = out_size / 16;             // 3,428,352 for B=4
    gather_out_kernel<<<(n16 + 255) / 256, 256>>>(coords, feat, out, M, n16);
}

// round 8
// speedup vs baseline: 1.2696x; 1.2696x over previous
#include <cuda_runtime.h>
#include <cuda_bf16.h>
#include <stdint.h>

// PointPillars BEV scatter as a full-output gather, channel-quad version.
//   out(B, C, H, W): out[b,c,y,x] = feat[map[b,y,x], c]  (or 0 if empty)
//
// R6: map cleared by a cudaMemsetAsync graph node (0xFF == -1) instead of a
// dedicated init kernel; gather identical to the best (R4) version.

#define BEV_H 496
#define BEV_W 432
#define C_CH  64
#define HW    (BEV_H * BEV_W)     // 214,272
#define HW4   (HW / 4)            // 53,568
#define MAXB  8

// Per-call scratch map, re-cleared and rebuilt on every launch.
__device__ int g_pillar_map[MAXB * HW];

// ---------------------------------------------------------------------------
// Kernel 1: scatter pillar indices (collision-free coords by construction)
// ---------------------------------------------------------------------------
__global__ void scatter_map_kernel(const int* __restrict__ coords, int M) {
    int m = blockIdx.x * blockDim.x + threadIdx.x;
    if (m < M) {
        int b = coords[3 * m + 0];
        int y = coords[3 * m + 1];
        int x = coords[3 * m + 2];
        g_pillar_map[b * HW + y * BEV_W + x] = m;
    }
}

// ---------------------------------------------------------------------------
// Kernel 2: gather. Thread i -> (b, c4, r):
//   b = batch, c4 = channel quad (0..15), r = cell quad within plane.
// One int4 map read, 4 LDG.128 feature reads, 4 coalesced STG.128 streaming
// stores into 4 consecutive channel planes.
// ---------------------------------------------------------------------------
__global__ void __launch_bounds__(256) gather_out_kernel(
    const float* __restrict__ feat,   // (M, 64)
    float* __restrict__ out,          // (B, 64, H, W)
    int n16)                          // out_size / 16
{
    int i = blockIdx.x * blockDim.x + threadIdx.x;
    if (i >= n16) return;

    int r  = i % HW4;                 // cell-quad index within plane
    int t  = i / HW4;                 // b*16 + c4
    int c4 = t & 15;
    int b  = t >> 4;

    // Coalesced 16B map read.
    int4 m4 = *reinterpret_cast<const int4*>(&g_pillar_map[b * HW + 4 * r]);

    // Clamp so loads are always in-bounds; select 0 afterward.
    int i0 = m4.x < 0 ? 0 : m4.x;
    int i1 = m4.y < 0 ? 0 : m4.y;
    int i2 = m4.z < 0 ? 0 : m4.z;
    int i3 = m4.w < 0 ? 0 : m4.w;

    int cbase = c4 * 4;
    float4 f0 = __ldg(reinterpret_cast<const float4*>(&feat[i0 * C_CH + cbase]));
    float4 f1 = __ldg(reinterpret_cast<const float4*>(&feat[i1 * C_CH + cbase]));
    float4 f2 = __ldg(reinterpret_cast<const float4*>(&feat[i2 * C_CH + cbase]));
    float4 f3 = __ldg(reinterpret_cast<const float4*>(&feat[i3 * C_CH + cbase]));

    const float4 z4 = make_float4(0.f, 0.f, 0.f, 0.f);
    if (m4.x < 0) f0 = z4;
    if (m4.y < 0) f1 = z4;
    if (m4.z < 0) f2 = z4;
    if (m4.w < 0) f3 = z4;

    // Transpose 4x4 in registers: per-channel vectors over the 4 cells.
    float4 o0 = make_float4(f0.x, f1.x, f2.x, f3.x);
    float4 o1 = make_float4(f0.y, f1.y, f2.y, f3.y);
    float4 o2 = make_float4(f0.z, f1.z, f2.z, f3.z);
    float4 o3 = make_float4(f0.w, f1.w, f2.w, f3.w);

    // Coalesced streaming stores into 4 channel planes.
    long base = (long)(b * C_CH + cbase) * HW + 4 * r;
    __stcs(reinterpret_cast<float4*>(&out[base + 0L * HW]), o0);
    __stcs(reinterpret_cast<float4*>(&out[base + 1L * HW]), o1);
    __stcs(reinterpret_cast<float4*>(&out[base + 2L * HW]), o2);
    __stcs(reinterpret_cast<float4*>(&out[base + 3L * HW]), o3);
}

// ---------------------------------------------------------------------------
// Launch
// Inputs: [0] voxel_coords (M,3) int32, [1] voxel_features (M,64) f32,
//         [2] batch_size scalar (B derived from out_size instead).
// Output: (B, 64, 496, 432) float32
// ---------------------------------------------------------------------------
extern "C" void kernel_launch(void* const* d_in, const int* in_sizes, int n_in,
                              void* d_out, int out_size) {
    const int*   coords = (const int*)d_in[0];
    const float* feat   = (const float*)d_in[1];
    float*       out    = (float*)d_out;

    int M = in_sizes[0] / 3;
    int B = out_size / (C_CH * HW);
    if (B < 1) B = 1;
    if (B > MAXB) B = MAXB;

    // Clear the map with a memset node: 0xFF bytes == -1 per int.
    // cudaGetSymbolAddress is a host-side query (capture-safe, no alloc).
    void* map_ptr = nullptr;
    cudaGetSymbolAddress(&map_ptr, g_pillar_map);
    cudaMemsetAsync(map_ptr, 0xFF, (size_t)B * HW * sizeof(int), 0);

    scatter_map_kernel<<<(M + 255) / 256, 256>>>(coords, M);

    int n16 = out_size / 16;             // 3,428,352 for B=4
    gather_out_kernel<<<(n16 + 255) / 256, 256>>>(feat, out, n16);
}